// round 5
// baseline (speedup 1.0000x reference)
#include <cuda_runtime.h>
#include <math.h>
#include <stdint.h>

#define B_ 32
#define N_ 4096
#define M_ 128
#define TOT_ (B_ * M_)       // 4096 matched pairs total
#define LSA_T 512
#define KPT (N_ / LSA_T)     // 8 columns per thread
#define NW_ (LSA_T / 32)     // 16 warps

// Cost matrix scratch, stored TRANSPOSED: cost_t[b][m][n] = cost[b][n][m],
// so the LSA relax over n is coalesced.
__device__ float g_cost[(size_t)B_ * M_ * N_];

// ---------------------------------------------------------------------------
// Kernel 1: cost matrix (full-chip parallel, one CTA per (b, m) row).
// cost_t[b][m][n] = -softmax(predict_scores[b,n,:])[scores[b,m]]
//                   + |pp[b,n,0]-pt[b,m,0]| + |pp[b,n,1]-pt[b,m,1]|
// ---------------------------------------------------------------------------
__global__ void cost_kernel(const float* __restrict__ ps,
                            const float* __restrict__ pp,
                            const int*   __restrict__ sc,
                            const float* __restrict__ pt) {
    int bm = blockIdx.x;            // 0 .. B*M-1
    int b  = bm >> 7;
    int m  = bm & (M_ - 1);
    int s  = sc[b * M_ + m];
    float qx = pt[(b * M_ + m) * 2 + 0];
    float qy = pt[(b * M_ + m) * 2 + 1];
    float* out = g_cost + (size_t)bm * N_;
    const float2* psb = ((const float2*)ps) + (size_t)b * N_;
    const float2* ppb = ((const float2*)pp) + (size_t)b * N_;
    for (int n = threadIdx.x; n < N_; n += blockDim.x) {
        float2 l = psb[n];
        float mx = fmaxf(l.x, l.y);
        float e0 = expf(l.x - mx);
        float e1 = expf(l.y - mx);
        float p  = ((s == 0) ? e0 : e1) / (e0 + e1);
        float2 q = ppb[n];
        float l1 = fabsf(q.x - qx) + fabsf(q.y - qy);
        out[n] = -p + l1;           // PRESENCE_W = L1_W = 1
    }
}

// ---------------------------------------------------------------------------
// Kernel 2: Jonker-Volgenant shortest augmenting path, one CTA per batch.
// Transposed problem: n = 128 rows (targets), m = 4096 cols (predictions).
// Float64 semantics bit-match the reference _lsa. Static smem (~43 KB).
// Output is emitted as FLOAT32 (harness compares in float dtype).
// ---------------------------------------------------------------------------
__global__ __launch_bounds__(LSA_T) void lsa_kernel(float* __restrict__ out) {
    const int b   = blockIdx.x;
    const int tid = threadIdx.x;

    __shared__ double        shortest[N_];      // 32 KB
    __shared__ double        u[M_];             // 1 KB
    __shared__ double        red_val[NW_];
    __shared__ int           red_idx[NW_];
    __shared__ int           col4row[M_];       // row -> col (or -1)
    __shared__ unsigned char pathSC[N_];        // bits[6:0] = path row, bit7 = SC
    __shared__ signed char   row4col[N_];       // col -> row (or -1)
    __shared__ unsigned char SR[M_];
    __shared__ int           s_i, s_sink;
    __shared__ double        s_minval;

    const float* costb = g_cost + (size_t)b * M_ * N_;
    const double INF = __longlong_as_double(0x7ff0000000000000ULL);

    double v_loc[KPT];                          // v[tid + 512k] in registers
    #pragma unroll
    for (int k = 0; k < KPT; ++k) v_loc[k] = 0.0;

    for (int j = tid; j < N_; j += LSA_T) row4col[j] = -1;
    for (int r = tid; r < M_; r += LSA_T) { u[r] = 0.0; col4row[r] = -1; }
    __syncthreads();

    for (int cur = 0; cur < M_; ++cur) {
        // ---- per-augmentation init ----
        #pragma unroll
        for (int k = 0; k < KPT; ++k) {
            int j = tid + k * LSA_T;
            shortest[j] = INF;
            pathSC[j]   = 0;
        }
        for (int r = tid; r < M_; r += LSA_T) SR[r] = 0;
        if (tid == 0) { s_i = cur; s_sink = -1; s_minval = 0.0; }
        __syncthreads();

        // ---- Dijkstra over columns ----
        while (true) {
            const int    i  = s_i;
            const double mv = s_minval;
            if (tid == 0) SR[i] = 1;
            const double u_i  = u[i];
            const float* crow = costb + (size_t)i * N_;

            double bval = INF;
            int    bidx = 0x7fffffff;
            #pragma unroll
            for (int k = 0; k < KPT; ++k) {
                int j = tid + k * LSA_T;
                if (!(pathSC[j] & 0x80)) {
                    // numpy op order: ((min_val + Cm[i,j]) - u[i]) - v[j]
                    double r = ((mv + (double)crow[j]) - u_i) - v_loc[k];
                    if (r < shortest[j]) {
                        shortest[j] = r;
                        pathSC[j]   = (unsigned char)i;   // SC bit is 0 here
                    }
                    double sv = shortest[j];
                    if (sv < bval) { bval = sv; bidx = j; } // ascending j keeps lowest idx
                }
            }
            // two-stage argmin reduce (tie-break: smaller index)
            #pragma unroll
            for (int off = 16; off > 0; off >>= 1) {
                double ov = __shfl_down_sync(0xffffffffu, bval, off);
                int    oi = __shfl_down_sync(0xffffffffu, bidx, off);
                if (ov < bval || (ov == bval && oi < bidx)) { bval = ov; bidx = oi; }
            }
            if ((tid & 31) == 0) { red_val[tid >> 5] = bval; red_idx[tid >> 5] = bidx; }
            __syncthreads();
            if (tid < 32) {
                bval = (tid < NW_) ? red_val[tid] : INF;
                bidx = (tid < NW_) ? red_idx[tid] : 0x7fffffff;
                #pragma unroll
                for (int off = 8; off > 0; off >>= 1) {
                    double ov = __shfl_down_sync(0xffffffffu, bval, off);
                    int    oi = __shfl_down_sync(0xffffffffu, bidx, off);
                    if (ov < bval || (ov == bval && oi < bidx)) { bval = ov; bidx = oi; }
                }
                if (tid == 0) {
                    int jmin = bidx;
                    s_minval = bval;
                    pathSC[jmin] |= 0x80;                 // mark SC
                    int rc = row4col[jmin];
                    if (rc < 0) s_sink = jmin; else s_i = rc;
                }
            }
            __syncthreads();
            if (s_sink >= 0) break;
        }

        // ---- dual update ----
        const double mv = s_minval;
        for (int r = tid; r < M_; r += LSA_T) {
            if (r == cur)    u[r] += mv;
            else if (SR[r])  u[r] += mv - shortest[col4row[r]];
        }
        #pragma unroll
        for (int k = 0; k < KPT; ++k) {
            int j = tid + k * LSA_T;
            if (pathSC[j] & 0x80) v_loc[k] -= mv - shortest[j];
        }
        __syncthreads();

        // ---- augment along alternating path (serial, short) ----
        if (tid == 0) {
            int j = s_sink;
            while (true) {
                int i2 = pathSC[j] & 0x7f;
                row4col[j] = (signed char)i2;
                int t = col4row[i2]; col4row[i2] = j; j = t;
                if (i2 == cur) break;
            }
        }
        __syncthreads();
    }

    // ---- emit (batch, src, tgt) as FLOAT32, sorted by src ----
    if (tid < M_) {
        int c = col4row[tid];
        int rank = 0;
        #pragma unroll 8
        for (int k = 0; k < M_; ++k) rank += (col4row[k] < c);
        int base = b * M_ + rank;
        out[0 * TOT_ + base] = (float)b;     // batch_idx
        out[1 * TOT_ + base] = (float)c;     // src_idx (N index)
        out[2 * TOT_ + base] = (float)tid;   // tgt_idx (M index)
    }
}

// ---------------------------------------------------------------------------
extern "C" void kernel_launch(void* const* d_in, const int* in_sizes, int n_in,
                              void* d_out, int out_size) {
    const float* ps = (const float*)d_in[0];  // predict_scores [B,N,2] f32
    const float* pp = (const float*)d_in[1];  // predict_points [B,N,2] f32
    const int*   sc = (const int*)  d_in[2];  // scores [B,M] i32
    const float* pt = (const float*)d_in[3];  // points [B,M,2] f32

    cost_kernel<<<B_ * M_, 256>>>(ps, pp, sc, pt);
    lsa_kernel<<<B_, LSA_T>>>((float*)d_out);
}

// round 6
// speedup vs baseline: 1.6962x; 1.6962x over previous
#include <cuda_runtime.h>
#include <math.h>
#include <stdint.h>

#define B_ 32
#define N_ 4096
#define M_ 128
#define TOT_ (B_ * M_)       // 4096 matched pairs total
#define LSA_T 512
#define KPT (N_ / LSA_T)     // 8 columns per thread (strided: j = tid + 512k)
#define NW_ (LSA_T / 32)     // 16 warps

// Cost matrix scratch, stored TRANSPOSED: cost_t[b][m][n] = cost[b][n][m].
__device__ float g_cost[(size_t)B_ * M_ * N_];

// ---------------------------------------------------------------------------
// Kernel 1: cost matrix (full-chip parallel, one CTA per (b, m) row).
// ---------------------------------------------------------------------------
__global__ void cost_kernel(const float* __restrict__ ps,
                            const float* __restrict__ pp,
                            const int*   __restrict__ sc,
                            const float* __restrict__ pt) {
    int bm = blockIdx.x;
    int b  = bm >> 7;
    int m  = bm & (M_ - 1);
    int s  = sc[b * M_ + m];
    float qx = pt[(b * M_ + m) * 2 + 0];
    float qy = pt[(b * M_ + m) * 2 + 1];
    float* out = g_cost + (size_t)bm * N_;
    const float2* psb = ((const float2*)ps) + (size_t)b * N_;
    const float2* ppb = ((const float2*)pp) + (size_t)b * N_;
    for (int n = threadIdx.x; n < N_; n += blockDim.x) {
        float2 l = psb[n];
        float mx = fmaxf(l.x, l.y);
        float e0 = expf(l.x - mx);
        float e1 = expf(l.y - mx);
        float p  = ((s == 0) ? e0 : e1) / (e0 + e1);
        float2 q = ppb[n];
        float l1 = fabsf(q.x - qx) + fabsf(q.y - qy);
        out[n] = -p + l1;
    }
}

// Order-preserving bijection double <-> uint64 (total order, exact).
__device__ __forceinline__ unsigned long long dkey(double x) {
    unsigned long long u = (unsigned long long)__double_as_longlong(x);
    unsigned long long m = (unsigned long long)((long long)u >> 63);
    return u ^ (m | 0x8000000000000000ULL);
}
__device__ __forceinline__ double dunkey(unsigned long long k) {
    unsigned long long u = (k & 0x8000000000000000ULL)
                         ? (k ^ 0x8000000000000000ULL) : ~k;
    return __longlong_as_double((long long)u);
}

#define INFKEY 0xFFF0000000000000ULL   /* dkey(+inf) */

// ---------------------------------------------------------------------------
// Kernel 2: Jonker-Volgenant, one CTA per batch. n=128 rows, m=4096 cols.
// FP64 values bit-match the reference; comparisons done on u64 keys (exact).
// One barrier per Dijkstra step (parity-double-buffered warp minima).
// Dual update via pop history (shortest[popped col] == its pop-time min).
// ---------------------------------------------------------------------------
__global__ __launch_bounds__(LSA_T) void lsa_kernel(float* __restrict__ out) {
    const int b   = blockIdx.x;
    const int tid = threadIdx.x;

    __shared__ unsigned long long skey[N_];        // 32 KB: key(shortest[j])
    __shared__ double             u[M_];           // 1 KB
    __shared__ unsigned long long red_key[2][NW_]; // parity double-buffer
    __shared__ int                red_idx[2][NW_];
    __shared__ unsigned long long hist_k[M_ + 1];  // pop-time min key
    __shared__ short              hist_j[M_ + 1];  // popped column
    __shared__ short              col4row[M_];     // row -> col (or -1)
    __shared__ signed char        row4col[N_];     // col -> row (or -1)
    __shared__ unsigned char      pathSC[N_];      // bits[6:0]=path row, bit7=SC

    const float* costb = g_cost + (size_t)b * M_ * N_;

    double v_loc[KPT];                             // v[tid + 512k] in registers
    #pragma unroll
    for (int k = 0; k < KPT; ++k) v_loc[k] = 0.0;

    for (int j = tid; j < N_; j += LSA_T) row4col[j] = -1;
    if (tid < M_) { u[tid] = 0.0; col4row[tid] = -1; }
    __syncthreads();

    for (int cur = 0; cur < M_; ++cur) {
        // ---- per-augmentation init (owner-only state; no barrier needed) ----
        #pragma unroll
        for (int k = 0; k < KPT; ++k) {
            int j = tid + k * LSA_T;
            skey[j]   = INFKEY;
            pathSC[j] = 0;
        }
        int    i   = cur;
        double mv  = 0.0;
        double u_i = u[cur];
        int    S   = 0;          // pops so far (uniform across threads)
        int    sink = -1;

        // ---- Dijkstra over columns: ONE barrier per step ----
        while (true) {
            const float* crow = costb + (size_t)i * N_;

            float c[KPT];                              // batched coalesced loads
            #pragma unroll
            for (int k = 0; k < KPT; ++k) c[k] = __ldg(crow + tid + k * LSA_T);

            unsigned long long bkey = ~0ULL;
            int                bidx = N_;
            #pragma unroll
            for (int k = 0; k < KPT; ++k) {
                int j = tid + k * LSA_T;
                unsigned char pb = pathSC[j];
                if (!(pb & 0x80)) {
                    // numpy op order: ((min_val + Cm[i,j]) - u[i]) - v[j]
                    double r = ((mv + (double)c[k]) - u_i) - v_loc[k];
                    unsigned long long rk = dkey(r);
                    unsigned long long sk = skey[j];
                    if (rk < sk) {                     // == (r < shortest[j])
                        skey[j]   = rk;
                        pathSC[j] = (unsigned char)i;  // SC bit is 0 here
                        sk = rk;
                    }
                    if (sk < bkey) { bkey = sk; bidx = j; }  // ascending j/thread
                }
            }
            // warp argmin (tie-break: smaller column index)
            #pragma unroll
            for (int off = 16; off > 0; off >>= 1) {
                unsigned long long ok = __shfl_down_sync(0xffffffffu, bkey, off);
                int                oi = __shfl_down_sync(0xffffffffu, bidx, off);
                if (ok < bkey || (ok == bkey && oi < bidx)) { bkey = ok; bidx = oi; }
            }
            const int p = S & 1;
            if ((tid & 31) == 0) { red_key[p][tid >> 5] = bkey; red_idx[p][tid >> 5] = bidx; }
            __syncthreads();

            // every thread scans the 16 warp minima -> identical decision
            unsigned long long kmin = red_key[p][0];
            int                jmin = red_idx[p][0];
            #pragma unroll
            for (int w = 1; w < NW_; ++w) {
                unsigned long long kk = red_key[p][w];
                int                jj = red_idx[p][w];
                if (kk < kmin || (kk == kmin && jj < jmin)) { kmin = kk; jmin = jj; }
            }
            if (tid == 0) { hist_k[S] = kmin; hist_j[S] = (short)jmin; }
            S++;
            if ((jmin & (LSA_T - 1)) == tid) pathSC[jmin] |= 0x80;  // owner marks SC
            mv = dunkey(kmin);
            int rc = row4col[jmin];
            if (rc < 0) { sink = jmin; break; }
            i   = rc;
            u_i = u[i];
            // no second barrier: cross-thread smem comms are only red_* (parity-
            // buffered, protected by the barrier chain) and owner-private state.
        }
        __syncthreads();    // hist / SC marks / relax all complete

        // ---- dual update from pop history ----
        const double mvf = mv;                         // uniform final min_val
        if (tid == cur) u[cur] += mvf;
        if (tid < S - 1) {                             // non-sink pops
            int js = hist_j[tid];
            int r  = row4col[js];                      // pre-augment matching
            u[r] += mvf - dunkey(hist_k[tid]);
        }
        for (int s = 0; s < S; ++s) {                  // v over SC (incl. sink: -0.0 exact)
            int js = hist_j[s];
            if ((js & (LSA_T - 1)) == tid)
                v_loc[js >> 9] -= mvf - dunkey(hist_k[s]);
        }
        __syncthreads();    // dual reads of row4col done before augment writes

        // ---- augment along alternating path ----
        if (tid == 0) {
            int j = sink;
            while (true) {
                int i2 = pathSC[j] & 0x7f;
                row4col[j] = (signed char)i2;
                int t = col4row[i2]; col4row[i2] = (short)j; j = t;
                if (i2 == cur) break;
            }
        }
        __syncthreads();
    }

    // ---- emit (batch, src, tgt) as FLOAT32, sorted by src ----
    if (tid < M_) {
        int c = col4row[tid];
        int rank = 0;
        #pragma unroll 8
        for (int k = 0; k < M_; ++k) rank += (col4row[k] < c);
        int base = b * M_ + rank;
        out[0 * TOT_ + base] = (float)b;
        out[1 * TOT_ + base] = (float)c;
        out[2 * TOT_ + base] = (float)tid;
    }
}

// ---------------------------------------------------------------------------
extern "C" void kernel_launch(void* const* d_in, const int* in_sizes, int n_in,
                              void* d_out, int out_size) {
    const float* ps = (const float*)d_in[0];
    const float* pp = (const float*)d_in[1];
    const int*   sc = (const int*)  d_in[2];
    const float* pt = (const float*)d_in[3];

    cost_kernel<<<B_ * M_, 256>>>(ps, pp, sc, pt);
    lsa_kernel<<<B_, LSA_T>>>((float*)d_out);
}